// round 7
// baseline (speedup 1.0000x reference)
#include <cuda_runtime.h>
#include <cstdint>
#include <math.h>

// Problem constants
#define Bb   256
#define Tt   1024
#define Hh   164
#define JH   82
#define NTH  704         // 22 warps: A = warps 0-10 (local k), B = warps 11-21 (peer k)
#define NCTA 128         // 64 clusters x 2
#define HBUF 2624        // 82 k-pairs * 32B per parity
#define RKW  3           // k-pairs in registers per thread
#define NSL  18          // smem weight slots per thread (21 - RKW)

// shared memory layout (bytes)
#define OFF_WSM   0
#define SZ_WSM    (NSL * 656 * 16)          // 188928: Wsm2[slot][wslot] = (wA,wB)
#define OFF_HQ    (OFF_WSM + SZ_WSM)        // 188928
#define SZ_HQ     (2 * HBUF + 32)           // 5280 (32B zero pad for k-padding)
#define OFF_GB    (OFF_HQ + SZ_HQ)          // 194208
#define SZ_GB     (656 * 2 * 16)            // 20992: gb4[wslot*2+ab] float4
#define OFF_PW    (OFF_GB + SZ_GB)          // 215200
#define SZ_PW     (2 * 11 * 16)             // 352: pwf[par][w][r]
#define OFF_PRFP  (OFF_PW + SZ_PW)          // 215552: peer pred sums [par][r]
#define SZ_PRFP   32
#define OFF_XQ    (OFF_PRFP + SZ_PRFP)      // 215584
#define SZ_XQ     (2 * 8 * 16)              // 256
#define OFF_WIH   (OFF_XQ + SZ_XQ)          // 215840
#define SZ_WIH    (14 * 164 * 4)            // 9184
#define OFF_W04   (OFF_WIH + SZ_WIH)        // 225024
#define SZ_W04    (82 * 16)
#define OFF_WO    (OFF_W04 + SZ_W04)        // 226336
#define SZ_WO     (82 * 4)
#define OFF_B2    (OFF_WO + SZ_WO)          // 226664
#define SZ_B2     (164 * 8)
#define OFF_MBAR  (OFF_B2 + SZ_B2)          // 227976
#define SMEM_TOTAL (OFF_MBAR + 16)          // 227992

typedef unsigned long long ull;

__device__ __forceinline__ float sigmoidf_(float v) {
    return 1.0f / (1.0f + expf(-v));
}
__device__ __forceinline__ ull pack2_(float a, float b) {
    ull r; asm("mov.b64 %0, {%1, %2};" : "=l"(r) : "f"(a), "f"(b)); return r;
}
__device__ __forceinline__ void unpack2_(ull v, float& a, float& b) {
    asm("mov.b64 {%0, %1}, %2;" : "=f"(a), "=f"(b) : "l"(v));
}
__device__ __forceinline__ void fma2_(ull& acc, ull a, ull b) {
    asm("fma.rn.f32x2 %0, %1, %2, %0;" : "+l"(acc) : "l"(a), "l"(b));
}
__device__ __forceinline__ void mbar_wait(uint32_t mbar, uint32_t parity) {
    uint32_t done;
    asm volatile(
        "{\n\t.reg .pred p;\n\t"
        "mbarrier.try_wait.parity.acquire.cluster.shared::cta.b64 p, [%1], %2;\n\t"
        "selp.b32 %0, 1, 0, p;\n\t}"
        : "=r"(done) : "r"(mbar), "r"(parity) : "memory");
    while (!done) {
        asm volatile(
            "{\n\t.reg .pred p;\n\t"
            "mbarrier.try_wait.parity.acquire.cluster.shared::cta.b64 p, [%1], %2, 0x989680;\n\t"
            "selp.b32 %0, 1, 0, p;\n\t}"
            : "=r"(done) : "r"(mbar), "r"(parity) : "memory");
    }
}

extern "C" __global__ void __launch_bounds__(NTH, 1) __cluster_dims__(2, 1, 1)
lstm_anom_kernel(const float* __restrict__ x,
                 const float* __restrict__ Wih,
                 const float* __restrict__ Whh,
                 const float* __restrict__ bih,
                 const float* __restrict__ bhh,
                 const float* __restrict__ Wout,
                 const float* __restrict__ bout,
                 float* __restrict__ out)
{
    extern __shared__ char smem[];
    ulonglong2* Wsm2 = (ulonglong2*)(smem + OFF_WSM);
    float4* gb4  = (float4*)(smem + OFF_GB);
    const float* gbf = (const float*)(smem + OFF_GB);
    float*  pwf  = (float*)(smem + OFF_PW);
    float*  prfp = (float*)(smem + OFF_PRFP);
    float*  xqf  = (float*)(smem + OFF_XQ);
    float*  wihs = (float*)(smem + OFF_WIH);
    float4* w04  = (float4*)(smem + OFF_W04);
    float*  wo   = (float*)(smem + OFF_WO);
    float2* b2   = (float2*)(smem + OFF_B2);

    const int tid       = threadIdx.x;
    const uint32_t rank = (uint32_t)(blockIdx.x & 1);
    const uint32_t peer = rank ^ 1u;
    const int cluster   = blockIdx.x >> 1;
    const int row0      = cluster * 4;

    const uint32_t smem_b = (uint32_t)__cvta_generic_to_shared(smem);
    const uint32_t mbar_b = smem_b + OFF_MBAR;
    uint32_t peer_b;
    asm("mapa.shared::cluster.u32 %0, %1, %2;" : "=r"(peer_b) : "r"(smem_b), "r"(peer));

    // ---------- roles ----------
    const int set  = (tid >= 352);               // 0 = local k-half, 1 = peer k-half
    const int idx  = tid - set * 352;
    const bool active = (idx < 328);
    const int g    = active ? (idx % 164) : 0;   // gate-row-pair id
    const int s    = active ? (idx / 164) : 0;   // k sub-half
    const int half = set ? (int)(rank ^ 1u) : (int)rank;
    const int kp0  = half * 41 + s * 21;         // first k-pair
    const int wslot = set * 328 + idx;           // unique compute-thread slot

    // ---------- one-time init ----------
    ull wregA[RKW], wregB[RKW];
    if (active) {
        int gt  = g / 82;
        int jj0 = g - gt * 82;
        int RA  = gt * Hh + (int)rank * JH + jj0;        // i (gt0) / f (gt1)
        int RB  = (gt + 2) * Hh + (int)rank * JH + jj0;  // g / o
        const ull* wrA = (const ull*)(Whh + (size_t)RA * Hh);
        const ull* wrB = (const ull*)(Whh + (size_t)RB * Hh);
#pragma unroll
        for (int kk = 0; kk < 21; kk++) {
            bool ok = (kk < 21 - s);            // s==1: last slot zero-padded
            ull vA = ok ? wrA[kp0 + kk] : 0ull;
            ull vB = ok ? wrB[kp0 + kk] : 0ull;
            if (kk < RKW) { wregA[kk] = vA; wregB[kk] = vB; }
            else Wsm2[(kk - RKW) * 656 + wslot] = make_ulonglong2(vA, vB);
        }
        if (set == 0 && s == 0) {
#pragma unroll
            for (int i = 1; i < 8; i++) {
                wihs[(0 * 7 + i - 1) * 164 + g] = Wih[RA * 8 + i];
                wihs[(1 * 7 + i - 1) * 164 + g] = Wih[RB * 8 + i];
            }
            b2[g] = make_float2(bih[RA] + bhh[RA], bih[RB] + bhh[RB]);
        }
    }
    if (tid < JH) {
        int base = (int)rank * JH + tid;
        w04[tid] = make_float4(Wih[(0 * Hh + base) * 8], Wih[(1 * Hh + base) * 8],
                               Wih[(2 * Hh + base) * 8], Wih[(3 * Hh + base) * 8]);
        wo[tid] = Wout[base];
    }
    for (int i2 = tid; i2 < (SZ_HQ / 4); i2 += NTH)
        ((float*)(smem + OFF_HQ))[i2] = 0.f;
    for (int i2 = tid; i2 < (SZ_PW / 4); i2 += NTH) pwf[i2] = 0.f;
    if (tid < 8) prfp[tid] = 0.f;
    if (tid < 32) {
        int i = tid >> 2, r = tid & 3;
        xqf[(0 * 8 + i) * 4 + r] = x[((size_t)((row0 + r) * Tt)) * 8 + i];
    }
    if (tid == 0) {
        asm volatile("mbarrier.init.shared.b64 [%0], 16;" :: "r"(mbar_b) : "memory");
        asm volatile("mbarrier.init.shared.b64 [%0], 16;" :: "r"(mbar_b + 8) : "memory");
    }
    const float bout_r = bout[0];
    float c_r = 0.f;                  // activation state, tid < 328: (jj, r)
    const int jj = tid >> 2, rr = tid & 3;
    const int wid = tid >> 5, lane = tid & 31;

    __syncthreads();
    asm volatile("barrier.cluster.arrive.aligned;" ::: "memory");
    asm volatile("barrier.cluster.wait.aligned;" ::: "memory");

    for (int t = 0; t < Tt; ++t) {
        const int cur = t & 1;
        const int nxt = cur ^ 1;

        if (set) {
            // ---- set B waits for peer crew (h-half + pred partial) ----
            mbar_wait(mbar_b + (uint32_t)(cur * 8), (uint32_t)((t >> 1) & 1));
            if (tid >= 680 && tid < 684) {
                // ---- pred finalize, anomaly fix, outputs ----
                int r = tid - 680, row = row0 + r;
                if (t > 0) {
                    float sown = 0.f;
#pragma unroll
                    for (int w = 0; w < 11; w++) sown += pwf[nxt * 44 + w * 4 + r];
                    float pred = sown + prfp[nxt * 4 + r] + bout_r;
                    float x0raw = xqf[(cur * 8 + 0) * 4 + r];
                    float flag = 0.f, x0 = x0raw;
                    if (fabsf(pred - x0raw) > 0.1f) { x0 = pred; flag = 1.f; }
                    xqf[(cur * 8 + 0) * 4 + r] = x0;
                    if (rank == 0) {
                        out[(size_t)row * Tt + (t - 1)] = pred;
                        out[(size_t)Bb * Tt + (size_t)row * Tt + t] = flag;
                    }
                } else if (rank == 0) {
                    out[(size_t)Bb * Tt + (size_t)row * Tt] = 0.f;
                }
            }
        } else if (!active) {
            // ---- crew (tid 328-351): push h + pred to peer, prefetch x ----
            int sp = tid - 328;
            if (sp < 12) {
                uint32_t lsrc = smem_b + (uint32_t)(OFF_HQ + cur * HBUF + (int)rank * 41 * 32);
                uint32_t rdst = peer_b + (uint32_t)(OFF_HQ + cur * HBUF + (int)rank * 41 * 32);
                for (int j2 = sp; j2 < 164; j2 += 12) {
                    ull v;
                    asm("ld.shared.u64 %0, [%1];" : "=l"(v) : "r"(lsrc + (uint32_t)(j2 * 8)));
                    asm volatile("st.shared::cluster.u64 [%0], %1;"
                                 :: "r"(rdst + (uint32_t)(j2 * 8)), "l"(v) : "memory");
                }
                asm volatile("mbarrier.arrive.release.cluster.shared::cluster.b64 _, [%0];"
                             :: "r"(peer_b + (uint32_t)(OFF_MBAR + cur * 8)) : "memory");
            } else if (sp < 16) {
                int r = sp - 12;
                float ssum = 0.f;
#pragma unroll
                for (int w = 0; w < 11; w++) ssum += pwf[nxt * 44 + w * 4 + r];
                asm volatile("st.shared::cluster.f32 [%0], %1;"
                             :: "r"(peer_b + (uint32_t)(OFF_PRFP + (nxt * 4 + r) * 4)),
                                "f"(ssum) : "memory");
                asm volatile("mbarrier.arrive.release.cluster.shared::cluster.b64 _, [%0];"
                             :: "r"(peer_b + (uint32_t)(OFF_MBAR + cur * 8)) : "memory");
            } else if (t + 1 < Tt) {
                int i = sp - 16;
#pragma unroll
                for (int r = 0; r < 4; r++)
                    xqf[(nxt * 8 + i) * 4 + r] =
                        x[((size_t)((row0 + r) * Tt + t + 1)) * 8 + i];
            }
        }

        if (active) {
            // ---- GEMV over this thread's 21 k-pairs ----
            ull acc[8];   // [ab*4 + r]
            if (set == 0 && s == 0) {
                float2 bb = b2[g];
                float a0 = bb.x, a1 = bb.x, a2 = bb.x, a3 = bb.x;
                float b0 = bb.y, b1 = bb.y, b2v = bb.y, b3 = bb.y;
                const float4* xv4 = (const float4*)(smem + OFF_XQ + cur * 128);
#pragma unroll
                for (int i = 1; i < 8; i++) {
                    float4 xv = xv4[i];
                    float wA = wihs[(0 * 7 + i - 1) * 164 + g];
                    float wB = wihs[(1 * 7 + i - 1) * 164 + g];
                    a0 += wA * xv.x; a1 += wA * xv.y; a2 += wA * xv.z; a3 += wA * xv.w;
                    b0 += wB * xv.x; b1 += wB * xv.y; b2v += wB * xv.z; b3 += wB * xv.w;
                }
                acc[0] = pack2_(a0, 0.f); acc[1] = pack2_(a1, 0.f);
                acc[2] = pack2_(a2, 0.f); acc[3] = pack2_(a3, 0.f);
                acc[4] = pack2_(b0, 0.f); acc[5] = pack2_(b1, 0.f);
                acc[6] = pack2_(b2v, 0.f); acc[7] = pack2_(b3, 0.f);
            } else {
#pragma unroll
                for (int q2 = 0; q2 < 8; q2++) acc[q2] = 0ull;
            }
            const char* hb = smem + OFF_HQ + cur * HBUF + kp0 * 32;
#pragma unroll
            for (int kk = 0; kk < RKW; kk++) {
                ulonglong2 h01 = *(const ulonglong2*)(hb + kk * 32);
                ulonglong2 h23 = *(const ulonglong2*)(hb + kk * 32 + 16);
                fma2_(acc[0], wregA[kk], h01.x); fma2_(acc[4], wregB[kk], h01.x);
                fma2_(acc[1], wregA[kk], h01.y); fma2_(acc[5], wregB[kk], h01.y);
                fma2_(acc[2], wregA[kk], h23.x); fma2_(acc[6], wregB[kk], h23.x);
                fma2_(acc[3], wregA[kk], h23.y); fma2_(acc[7], wregB[kk], h23.y);
            }
#pragma unroll 9
            for (int kk = RKW; kk < 21; kk++) {
                ulonglong2 w2 = Wsm2[(kk - RKW) * 656 + wslot];
                ulonglong2 h01 = *(const ulonglong2*)(hb + kk * 32);
                ulonglong2 h23 = *(const ulonglong2*)(hb + kk * 32 + 16);
                fma2_(acc[0], w2.x, h01.x); fma2_(acc[4], w2.y, h01.x);
                fma2_(acc[1], w2.x, h01.y); fma2_(acc[5], w2.y, h01.y);
                fma2_(acc[2], w2.x, h23.x); fma2_(acc[6], w2.y, h23.x);
                fma2_(acc[3], w2.x, h23.y); fma2_(acc[7], w2.y, h23.y);
            }
            float lo, hi;
            float4 vA, vB;
            unpack2_(acc[0], lo, hi); vA.x = lo + hi;
            unpack2_(acc[1], lo, hi); vA.y = lo + hi;
            unpack2_(acc[2], lo, hi); vA.z = lo + hi;
            unpack2_(acc[3], lo, hi); vA.w = lo + hi;
            unpack2_(acc[4], lo, hi); vB.x = lo + hi;
            unpack2_(acc[5], lo, hi); vB.y = lo + hi;
            unpack2_(acc[6], lo, hi); vB.z = lo + hi;
            unpack2_(acc[7], lo, hi); vB.w = lo + hi;
            gb4[wslot * 2 + 0] = vA;
            gb4[wslot * 2 + 1] = vB;
        }
        __syncthreads();   // gate partials + fixed x0 published

        // ---- activation, state update, local h store, pred partials ----
        if (tid < 328) {
            float x0 = xqf[(cur * 8 + 0) * 4 + rr];
            float gi = 0.f, gF = 0.f, gg = 0.f, go = 0.f;
#pragma unroll
            for (int ss = 0; ss < 4; ss++) {
                int base = (ss >> 1) * 328 + (ss & 1) * 164;
                gi += gbf[((base + jj) * 2 + 0) * 4 + rr];
                gF += gbf[((base + 82 + jj) * 2 + 0) * 4 + rr];
                gg += gbf[((base + jj) * 2 + 1) * 4 + rr];
                go += gbf[((base + 82 + jj) * 2 + 1) * 4 + rr];
            }
            float4 wz = w04[jj];
            gi += wz.x * x0; gF += wz.y * x0; gg += wz.z * x0; go += wz.w * x0;
            float iv = sigmoidf_(gi);
            float fv = sigmoidf_(gF);
            float gv = tanhf(gg);
            float ov = sigmoidf_(go);
            c_r = fv * c_r + iv * gv;
            float hn = ov * tanhf(c_r);

            int kg = (int)rank * JH + jj;
            uint32_t hoff = (uint32_t)(OFF_HQ + nxt * HBUF
                                       + (kg >> 1) * 32 + rr * 8 + (kg & 1) * 4);
            *(float*)(smem + hoff) = hn;     // local only; crew pushes next step

            float p = hn * wo[jj];
            if (wid < 10) {
                p += __shfl_xor_sync(0xffffffffu, p, 16);
                p += __shfl_xor_sync(0xffffffffu, p, 8);
                p += __shfl_xor_sync(0xffffffffu, p, 4);
            } else {
                p += __shfl_xor_sync(0xffu, p, 4);
            }
            if (lane < 4) pwf[cur * 44 + wid * 4 + lane] = p;
        }
        __syncthreads();   // h[nxt] + pwf[cur] published locally
    }

    // ---- tail: exchange final pred partials, write column Tt-1 ----
    if (tid >= 328 && tid < 352) {
        int sp = tid - 328;
        if (sp < 12) {
            asm volatile("mbarrier.arrive.release.cluster.shared::cluster.b64 _, [%0];"
                         :: "r"(peer_b + (uint32_t)OFF_MBAR) : "memory");
        } else if (sp < 16) {
            int r = sp - 12;
            float ssum = 0.f;
#pragma unroll
            for (int w = 0; w < 11; w++) ssum += pwf[1 * 44 + w * 4 + r];
            asm volatile("st.shared::cluster.f32 [%0], %1;"
                         :: "r"(peer_b + (uint32_t)(OFF_PRFP + (1 * 4 + r) * 4)),
                            "f"(ssum) : "memory");
            asm volatile("mbarrier.arrive.release.cluster.shared::cluster.b64 _, [%0];"
                         :: "r"(peer_b + (uint32_t)OFF_MBAR) : "memory");
        }
    }
    if (tid >= 680 && tid < 684) {
        mbar_wait(mbar_b, (uint32_t)((Tt >> 1) & 1));
        if (rank == 0) {
            int r = tid - 680;
            float sown = 0.f;
#pragma unroll
            for (int w = 0; w < 11; w++) sown += pwf[1 * 44 + w * 4 + r];
            float pred = sown + prfp[1 * 4 + r] + bout_r;
            out[(size_t)(row0 + r) * Tt + (Tt - 1)] = pred;
        }
    }
}

extern "C" void kernel_launch(void* const* d_in, const int* in_sizes, int n_in,
                              void* d_out, int out_size) {
    (void)in_sizes; (void)n_in; (void)out_size;
    cudaFuncSetAttribute(lstm_anom_kernel,
                         cudaFuncAttributeMaxDynamicSharedMemorySize, SMEM_TOTAL);
    lstm_anom_kernel<<<NCTA, NTH, SMEM_TOTAL>>>(
        (const float*)d_in[0],   // x
        (const float*)d_in[1],   // W_ih
        (const float*)d_in[2],   // W_hh
        (const float*)d_in[3],   // b_ih
        (const float*)d_in[4],   // b_hh
        (const float*)d_in[5],   // W_out
        (const float*)d_in[6],   // b_out
        (float*)d_out);
}

// round 8
// speedup vs baseline: 1.4176x; 1.4176x over previous
#include <cuda_runtime.h>
#include <cstdint>
#include <math.h>

// Problem constants
#define Bb   256
#define Tt   1024
#define Hh   164
#define JH   82          // hidden slice per CTA (M-split across 2-CTA cluster)
#define KHP  41          // k-pairs per k-half
#define RKK  22          // k-pairs in registers per thread
#define SKK  (KHP - RKK) // 19 k-pairs in smem
#define NTH  384         // 12 warps: wg0 = warps 0-5 (local k), wg1 = warps 6-11 (peer k)
#define NCTA 128         // 64 clusters x 2
#define HBUF 2624        // 82 k-pairs * 32B per parity

// shared memory layout (bytes)
#define OFF_WSM   0
#define SZ_WSM    (SKK * 328 * 16)          // 99712: Wsm2[kks][wg*164+g] = (wA,wB)
#define OFF_HQ    (OFF_WSM + SZ_WSM)        // 99712
#define SZ_HQ     (2 * HBUF)                // 5248
#define OFF_GB    (OFF_HQ + SZ_HQ)          // 104960
#define SZ_GB     (2 * 2 * 164 * 16)        // 10496: gb4[(wg*2+ab)*164+g]
#define OFF_PW    (OFF_GB + SZ_GB)          // 115456
#define SZ_PW     (2 * 2 * 11 * 16)         // 704: pwf[par][side][w][r]
#define OFF_XQ    (OFF_PW + SZ_PW)          // 116160
#define SZ_XQ     (2 * 8 * 16)              // 256
#define OFF_WIH   (OFF_XQ + SZ_XQ)          // 116416
#define SZ_WIH    (14 * 164 * 4)            // 9184: wihs[(ab*7+i-1)*164+g]
#define OFF_W04   (OFF_WIH + SZ_WIH)        // 125600
#define SZ_W04    (82 * 16)                 // w_ih[:,0] per gate float4 per jj
#define OFF_WO    (OFF_W04 + SZ_W04)        // 126912
#define SZ_WO     (82 * 4)
#define OFF_B2    (OFF_WO + SZ_WO)          // 127240: (biasA,biasB) float2 per g
#define SZ_B2     (164 * 8)
#define OFF_MBAR  (OFF_B2 + SZ_B2)          // 128552
#define SMEM_TOTAL (OFF_MBAR + 16)

typedef unsigned long long ull;

__device__ __forceinline__ float sigmoidf_(float v) {
    return 1.0f / (1.0f + expf(-v));
}
__device__ __forceinline__ ull pack2_(float a, float b) {
    ull r; asm("mov.b64 %0, {%1, %2};" : "=l"(r) : "f"(a), "f"(b)); return r;
}
__device__ __forceinline__ void unpack2_(ull v, float& a, float& b) {
    asm("mov.b64 {%0, %1}, %2;" : "=f"(a), "=f"(b) : "l"(v));
}
__device__ __forceinline__ void fma2_(ull& acc, ull a, ull b) {
    asm("fma.rn.f32x2 %0, %1, %2, %0;" : "+l"(acc) : "l"(a), "l"(b));
}
__device__ __forceinline__ void st_remote_f32(uint32_t local_addr, uint32_t peer, float v) {
    uint32_t ra;
    asm("mapa.shared::cluster.u32 %0, %1, %2;" : "=r"(ra) : "r"(local_addr), "r"(peer));
    asm volatile("st.shared::cluster.f32 [%0], %1;" :: "r"(ra), "f"(v) : "memory");
}
__device__ __forceinline__ void mbar_arrive_release(uint32_t remote_mbar) {
    asm volatile("mbarrier.arrive.release.cluster.shared::cluster.b64 _, [%0];"
                 :: "r"(remote_mbar) : "memory");
}
__device__ __forceinline__ void mbar_wait(uint32_t mbar, uint32_t parity) {
    uint32_t done;
    asm volatile(
        "{\n\t.reg .pred p;\n\t"
        "mbarrier.try_wait.parity.acquire.cluster.shared::cta.b64 p, [%1], %2;\n\t"
        "selp.b32 %0, 1, 0, p;\n\t}"
        : "=r"(done) : "r"(mbar), "r"(parity) : "memory");
    while (!done) {
        asm volatile(
            "{\n\t.reg .pred p;\n\t"
            "mbarrier.try_wait.parity.acquire.cluster.shared::cta.b64 p, [%1], %2, 0x989680;\n\t"
            "selp.b32 %0, 1, 0, p;\n\t}"
            : "=r"(done) : "r"(mbar), "r"(parity) : "memory");
    }
}

extern "C" __global__ void __launch_bounds__(NTH, 1) __cluster_dims__(2, 1, 1)
lstm_anom_kernel(const float* __restrict__ x,
                 const float* __restrict__ Wih,
                 const float* __restrict__ Whh,
                 const float* __restrict__ bih,
                 const float* __restrict__ bhh,
                 const float* __restrict__ Wout,
                 const float* __restrict__ bout,
                 float* __restrict__ out)
{
    extern __shared__ char smem[];
    ulonglong2* Wsm2 = (ulonglong2*)(smem + OFF_WSM);
    float4* gb4  = (float4*)(smem + OFF_GB);
    const float* gbf = (const float*)(smem + OFF_GB);
    float*  pwf  = (float*)(smem + OFF_PW);
    float*  xqf  = (float*)(smem + OFF_XQ);
    float*  wihs = (float*)(smem + OFF_WIH);
    float4* w04  = (float4*)(smem + OFF_W04);
    float*  wo   = (float*)(smem + OFF_WO);
    float2* b2   = (float2*)(smem + OFF_B2);

    const int tid       = threadIdx.x;
    const uint32_t rank = (uint32_t)(blockIdx.x & 1);
    const uint32_t peer = rank ^ 1u;
    const int cluster   = blockIdx.x >> 1;
    const int row0      = cluster * 4;

    const uint32_t smem_b = (uint32_t)__cvta_generic_to_shared(smem);
    const uint32_t mbar_b = smem_b + OFF_MBAR;
    uint32_t peer_mbar;
    asm("mapa.shared::cluster.u32 %0, %1, %2;" : "=r"(peer_mbar) : "r"(mbar_b), "r"(peer));

    // ---------- roles ----------
    const int wg = (tid >= 192);           // 0 = local-k warps (0-5), 1 = peer-k (6-11)
    const int g  = tid - wg * 192;         // gate-row-pair id; active iff g < 164
    const bool active = (g < 164);
    const int kr  = wg ? (int)(rank ^ 1u) : (int)rank;   // which global k-half
    const int kp0 = kr * KHP;

    // ---------- one-time init ----------
    ull wregA[RKK], wregB[RKK];
    if (active) {
        int gt  = g / JH;
        int jj0 = g - gt * JH;
        int RA  = gt * Hh + (int)rank * JH + jj0;        // gate i (gt0) / f (gt1)
        int RB  = (gt + 2) * Hh + (int)rank * JH + jj0;  // gate g / o
        const ull* wrA = (const ull*)(Whh + (size_t)RA * Hh) + kp0;
        const ull* wrB = (const ull*)(Whh + (size_t)RB * Hh) + kp0;
#pragma unroll
        for (int kk = 0; kk < RKK; kk++) { wregA[kk] = wrA[kk]; wregB[kk] = wrB[kk]; }
        for (int kk = RKK; kk < KHP; kk++)
            Wsm2[(kk - RKK) * 328 + wg * 164 + g] = make_ulonglong2(wrA[kk], wrB[kk]);
        if (wg == 0) {
#pragma unroll
            for (int i = 1; i < 8; i++) {
                wihs[(0 * 7 + i - 1) * 164 + g] = Wih[RA * 8 + i];
                wihs[(1 * 7 + i - 1) * 164 + g] = Wih[RB * 8 + i];
            }
            b2[g] = make_float2(bih[RA] + bhh[RA], bih[RB] + bhh[RB]);
        }
    }
    if (tid < JH) {
        int base = (int)rank * JH + tid;
        w04[tid] = make_float4(Wih[(0 * Hh + base) * 8], Wih[(1 * Hh + base) * 8],
                               Wih[(2 * Hh + base) * 8], Wih[(3 * Hh + base) * 8]);
        wo[tid] = Wout[base];
    }
    for (int idx = tid; idx < (SZ_HQ / 4); idx += NTH)
        ((float*)(smem + OFF_HQ))[idx] = 0.f;
    for (int idx = tid; idx < (SZ_PW / 4); idx += NTH) pwf[idx] = 0.f;
    if (tid < 32) {
        int i = tid >> 2, r = tid & 3;
        xqf[(0 * 8 + i) * 4 + r] = x[((size_t)((row0 + r) * Tt)) * 8 + i];
    }
    if (tid == 0) {
        // 328 per-thread release-arrivals per step
        asm volatile("mbarrier.init.shared.b64 [%0], 328;" :: "r"(mbar_b) : "memory");
        asm volatile("mbarrier.init.shared.b64 [%0], 328;" :: "r"(mbar_b + 8) : "memory");
    }
    const float bout_r = bout[0];
    float c_r = 0.f;                  // per (jj, r) for tid < 328
    const int jj = tid >> 2, rr = tid & 3;
    const int wid = tid >> 5, lane = tid & 31;

    __syncthreads();
    asm volatile("barrier.cluster.arrive.aligned;" ::: "memory");
    asm volatile("barrier.cluster.wait.aligned;" ::: "memory");

    for (int t = 0; t < Tt; ++t) {
        const int cur = t & 1;
        const int nxt = cur ^ 1;

        // only peer-k warps (6-11) wait: spares + peer-half GEMV need peer data.
        if (wg && t)
            mbar_wait(mbar_b + (uint32_t)(((t - 1) & 1) * 8), (uint32_t)(((t - 1) >> 1) & 1));

        if (active) {
            // ---- GEMV over this thread's k-half ----
            ull accA[4], accB[4];
            if (wg == 0) {
                float2 bb = b2[g];
                float a0 = bb.x, a1 = bb.x, a2 = bb.x, a3 = bb.x;
                float b0 = bb.y, b1 = bb.y, b2v = bb.y, b3 = bb.y;
                const float4* xv4 = (const float4*)(smem + OFF_XQ + cur * 128);
#pragma unroll
                for (int i = 1; i < 8; i++) {
                    float4 xv = xv4[i];
                    float wA = wihs[(0 * 7 + i - 1) * 164 + g];
                    float wB = wihs[(1 * 7 + i - 1) * 164 + g];
                    a0 += wA * xv.x; a1 += wA * xv.y; a2 += wA * xv.z; a3 += wA * xv.w;
                    b0 += wB * xv.x; b1 += wB * xv.y; b2v += wB * xv.z; b3 += wB * xv.w;
                }
                accA[0] = pack2_(a0, 0.f); accA[1] = pack2_(a1, 0.f);
                accA[2] = pack2_(a2, 0.f); accA[3] = pack2_(a3, 0.f);
                accB[0] = pack2_(b0, 0.f); accB[1] = pack2_(b1, 0.f);
                accB[2] = pack2_(b2v, 0.f); accB[3] = pack2_(b3, 0.f);
            } else {
#pragma unroll
                for (int s = 0; s < 4; s++) { accA[s] = 0ull; accB[s] = 0ull; }
            }
            const ulonglong2* hp =
                (const ulonglong2*)(smem + OFF_HQ + cur * HBUF + kp0 * 32);
#pragma unroll
            for (int kk = 0; kk < RKK; kk++) {
                ulonglong2 h01 = hp[2 * kk];
                ulonglong2 h23 = hp[2 * kk + 1];
                fma2_(accA[0], wregA[kk], h01.x); fma2_(accB[0], wregB[kk], h01.x);
                fma2_(accA[1], wregA[kk], h01.y); fma2_(accB[1], wregB[kk], h01.y);
                fma2_(accA[2], wregA[kk], h23.x); fma2_(accB[2], wregB[kk], h23.x);
                fma2_(accA[3], wregA[kk], h23.y); fma2_(accB[3], wregB[kk], h23.y);
            }
#pragma unroll
            for (int kk = RKK; kk < KHP; kk++) {
                ulonglong2 w2 = Wsm2[(kk - RKK) * 328 + wg * 164 + g];
                ulonglong2 h01 = hp[2 * kk];
                ulonglong2 h23 = hp[2 * kk + 1];
                fma2_(accA[0], w2.x, h01.x); fma2_(accB[0], w2.y, h01.x);
                fma2_(accA[1], w2.x, h01.y); fma2_(accB[1], w2.y, h01.y);
                fma2_(accA[2], w2.x, h23.x); fma2_(accB[2], w2.y, h23.x);
                fma2_(accA[3], w2.x, h23.y); fma2_(accB[3], w2.y, h23.y);
            }
            float lo, hi;
            float4 vA, vB;
            unpack2_(accA[0], lo, hi); vA.x = lo + hi;
            unpack2_(accA[1], lo, hi); vA.y = lo + hi;
            unpack2_(accA[2], lo, hi); vA.z = lo + hi;
            unpack2_(accA[3], lo, hi); vA.w = lo + hi;
            unpack2_(accB[0], lo, hi); vB.x = lo + hi;
            unpack2_(accB[1], lo, hi); vB.y = lo + hi;
            unpack2_(accB[2], lo, hi); vB.z = lo + hi;
            unpack2_(accB[3], lo, hi); vB.w = lo + hi;
            gb4[(wg * 2 + 0) * 164 + g] = vA;
            gb4[(wg * 2 + 1) * 164 + g] = vB;
        } else if (tid >= 356) {
            // ---- spares (warp 11 tail): pred finalize, anomaly fix, x prefetch ----
            int sp = tid - 356;
            if (sp < 4) {
                int r = sp, row = row0 + r;
                if (t > 0) {
                    float pred = bout_r;
#pragma unroll
                    for (int w = 0; w < 11; w++) {
                        pred += pwf[((nxt * 2 + 0) * 11 + w) * 4 + r];
                        pred += pwf[((nxt * 2 + 1) * 11 + w) * 4 + r];
                    }
                    float x0raw = xqf[(cur * 8 + 0) * 4 + r];
                    float flag = 0.f, x0 = x0raw;
                    if (fabsf(pred - x0raw) > 0.1f) { x0 = pred; flag = 1.f; }
                    xqf[(cur * 8 + 0) * 4 + r] = x0;
                    if (rank == 0) {
                        out[(size_t)row * Tt + (t - 1)] = pred;
                        out[(size_t)Bb * Tt + (size_t)row * Tt + t] = flag;
                    }
                } else if (rank == 0) {
                    out[(size_t)Bb * Tt + (size_t)row * Tt] = 0.f;
                }
            } else if (sp >= 8 && sp < 16 && (t + 1 < Tt)) {
                int i = sp - 8;
#pragma unroll
                for (int r = 0; r < 4; r++)
                    xqf[(nxt * 8 + i) * 4 + r] =
                        x[((size_t)((row0 + r) * Tt + t + 1)) * 8 + i];
            }
        }
        __syncthreads();   // gate partials + fixed x0 published

        // ---- activation, state update, h exchange, pred partials (tid < 328) ----
        if (tid < 328) {
            float x0 = xqf[(cur * 8 + 0) * 4 + rr];
            float4 wz = w04[jj];
            float gi = gbf[((0 * 2 + 0) * 164 + jj) * 4 + rr]
                     + gbf[((1 * 2 + 0) * 164 + jj) * 4 + rr] + wz.x * x0;
            float gF = gbf[((0 * 2 + 0) * 164 + jj + 82) * 4 + rr]
                     + gbf[((1 * 2 + 0) * 164 + jj + 82) * 4 + rr] + wz.y * x0;
            float gg = gbf[((0 * 2 + 1) * 164 + jj) * 4 + rr]
                     + gbf[((1 * 2 + 1) * 164 + jj) * 4 + rr] + wz.z * x0;
            float go = gbf[((0 * 2 + 1) * 164 + jj + 82) * 4 + rr]
                     + gbf[((1 * 2 + 1) * 164 + jj + 82) * 4 + rr] + wz.w * x0;
            float iv = sigmoidf_(gi);
            float fv = sigmoidf_(gF);
            float gv = tanhf(gg);
            float ov = sigmoidf_(go);
            c_r = fv * c_r + iv * gv;
            float hn = ov * tanhf(c_r);

            int kg = (int)rank * JH + jj;
            uint32_t hoff = (uint32_t)(OFF_HQ + nxt * HBUF
                                       + (kg >> 1) * 32 + rr * 8 + (kg & 1) * 4);
            *(float*)(smem + hoff) = hn;
            st_remote_f32(smem_b + hoff, peer, hn);

            float p = hn * wo[jj];
            if (wid < 10) {
                p += __shfl_xor_sync(0xffffffffu, p, 16);
                p += __shfl_xor_sync(0xffffffffu, p, 8);
                p += __shfl_xor_sync(0xffffffffu, p, 4);
            } else {
                p += __shfl_xor_sync(0xffu, p, 4);
            }
            if (lane < 4) {
                uint32_t po0 = (uint32_t)(OFF_PW + (((cur * 2 + 0) * 11 + wid) * 4 + lane) * 4);
                uint32_t po1 = (uint32_t)(OFF_PW + (((cur * 2 + 1) * 11 + wid) * 4 + lane) * 4);
                *(float*)(smem + po0) = p;            // own side
                st_remote_f32(smem_b + po1, peer, p); // peer's side-1
            }
            // per-thread release-arrive: orders THIS thread's remote stores;
            // peer's set-B wake accumulates during our activation window.
            mbar_arrive_release(peer_mbar + (uint32_t)(cur * 8));
        }
        __syncthreads();   // local h/pw writes visible for next-step set A
    }

    // ---- tail: final prediction at column Tt-1 ----
    mbar_wait(mbar_b + (uint32_t)(((Tt - 1) & 1) * 8), (uint32_t)(((Tt - 1) >> 1) & 1));
    if (rank == 0 && tid < 4) {
        int par = (Tt - 1) & 1;
        float pred = bout_r;
#pragma unroll
        for (int w = 0; w < 11; w++) {
            pred += pwf[((par * 2 + 0) * 11 + w) * 4 + tid];
            pred += pwf[((par * 2 + 1) * 11 + w) * 4 + tid];
        }
        out[(size_t)(row0 + tid) * Tt + (Tt - 1)] = pred;
    }
}

extern "C" void kernel_launch(void* const* d_in, const int* in_sizes, int n_in,
                              void* d_out, int out_size) {
    (void)in_sizes; (void)n_in; (void)out_size;
    cudaFuncSetAttribute(lstm_anom_kernel,
                         cudaFuncAttributeMaxDynamicSharedMemorySize, SMEM_TOTAL);
    lstm_anom_kernel<<<NCTA, NTH, SMEM_TOTAL>>>(
        (const float*)d_in[0],   // x
        (const float*)d_in[1],   // W_ih
        (const float*)d_in[2],   // W_hh
        (const float*)d_in[3],   // b_ih
        (const float*)d_in[4],   // b_hh
        (const float*)d_in[5],   // W_out
        (const float*)d_in[6],   // b_out
        (float*)d_out);
}

// round 9
// speedup vs baseline: 1.6329x; 1.1519x over previous
#include <cuda_runtime.h>
#include <cstdint>
#include <math.h>

// Problem constants
#define Bb   256
#define Tt   1024
#define Hh   164
#define JH   82          // hidden slice per CTA (M-split across 2-CTA cluster)
#define NTH  384         // 12 warps; 328 compute threads
#define NCTA 128         // 64 clusters x 2
#define HSL  84          // h k-pair slots per parity (82 real + 2 zero pad)
#define HBUF (HSL * 32)  // 2688
#define RPW  11          // k-pairs in registers per window
#define SPW  10          // k-pairs in smem per window

// shared memory layout (bytes)
#define OFF_WSM   0
#define SZ_WSM    (2 * SPW * 328 * 16)      // 104960: Wsm2[w*SPW+s][tid] = (wA,wB)
#define OFF_HQ    (OFF_WSM + SZ_WSM)        // 104960
#define SZ_HQ     (2 * HBUF)                // 5376
#define OFF_GB    (OFF_HQ + SZ_HQ)          // 110336
#define SZ_GB     (656 * 16)                // 10496: gb4[(u*2+ab)*164+g]
#define OFF_PW    (OFF_GB + SZ_GB)          // 120832
#define SZ_PW     (2 * 11 * 16)             // 352: pwf[par][w][r]
#define OFF_PRFP  (OFF_PW + SZ_PW)          // 121184: peer pred sums [par][r]
#define SZ_PRFP   32
#define OFF_XQ    (OFF_PRFP + SZ_PRFP)      // 121216
#define SZ_XQ     (2 * 8 * 16)              // 256
#define OFF_WIH   (OFF_XQ + SZ_XQ)          // 121472
#define SZ_WIH    (14 * 164 * 4)            // 9184: wihs[(ab*7+i-1)*164+g]
#define OFF_W04   (OFF_WIH + SZ_WIH)        // 130656
#define SZ_W04    (82 * 16)
#define OFF_WO    (OFF_W04 + SZ_W04)        // 131968
#define SZ_WO     (82 * 4)
#define OFF_B2    (OFF_WO + SZ_WO)          // 132296
#define SZ_B2     (164 * 8)
#define OFF_MBAR  (OFF_B2 + SZ_B2)          // 133608
#define SMEM_TOTAL (OFF_MBAR + 16)          // 133624

typedef unsigned long long ull;

__device__ __forceinline__ float sigmoidf_(float v) {
    return 1.0f / (1.0f + expf(-v));
}
__device__ __forceinline__ ull pack2_(float a, float b) {
    ull r; asm("mov.b64 %0, {%1, %2};" : "=l"(r) : "f"(a), "f"(b)); return r;
}
__device__ __forceinline__ void unpack2_(ull v, float& a, float& b) {
    asm("mov.b64 {%0, %1}, %2;" : "=f"(a), "=f"(b) : "l"(v));
}
__device__ __forceinline__ void fma2_(ull& acc, ull a, ull b) {
    asm("fma.rn.f32x2 %0, %1, %2, %0;" : "+l"(acc) : "l"(a), "l"(b));
}
__device__ __forceinline__ ull ld_smem_u64(uint32_t addr) {
    ull v; asm volatile("ld.shared.u64 %0, [%1];" : "=l"(v) : "r"(addr)); return v;
}
__device__ __forceinline__ void st_remote_u64(uint32_t raddr, ull v) {
    asm volatile("st.shared::cluster.u64 [%0], %1;" :: "r"(raddr), "l"(v) : "memory");
}
__device__ __forceinline__ void st_remote_f32d(uint32_t raddr, float v) {
    asm volatile("st.shared::cluster.f32 [%0], %1;" :: "r"(raddr), "f"(v) : "memory");
}
__device__ __forceinline__ void mbar_arrive_release(uint32_t remote_mbar) {
    asm volatile("mbarrier.arrive.release.cluster.shared::cluster.b64 _, [%0];"
                 :: "r"(remote_mbar) : "memory");
}
__device__ __forceinline__ void mbar_wait(uint32_t mbar, uint32_t parity) {
    uint32_t done;
    asm volatile(
        "{\n\t.reg .pred p;\n\t"
        "mbarrier.try_wait.parity.acquire.cluster.shared::cta.b64 p, [%1], %2;\n\t"
        "selp.b32 %0, 1, 0, p;\n\t}"
        : "=r"(done) : "r"(mbar), "r"(parity) : "memory");
    while (!done) {
        asm volatile(
            "{\n\t.reg .pred p;\n\t"
            "mbarrier.try_wait.parity.acquire.cluster.shared::cta.b64 p, [%1], %2, 0x989680;\n\t"
            "selp.b32 %0, 1, 0, p;\n\t}"
            : "=r"(done) : "r"(mbar), "r"(parity) : "memory");
    }
}

extern "C" __global__ void __launch_bounds__(NTH, 1) __cluster_dims__(2, 1, 1)
lstm_anom_kernel(const float* __restrict__ x,
                 const float* __restrict__ Wih,
                 const float* __restrict__ Whh,
                 const float* __restrict__ bih,
                 const float* __restrict__ bhh,
                 const float* __restrict__ Wout,
                 const float* __restrict__ bout,
                 float* __restrict__ out)
{
    extern __shared__ char smem[];
    ulonglong2* Wsm2 = (ulonglong2*)(smem + OFF_WSM);
    float4* gb4  = (float4*)(smem + OFF_GB);
    const float* gbf = (const float*)(smem + OFF_GB);
    float*  pwf  = (float*)(smem + OFF_PW);
    float*  prfp = (float*)(smem + OFF_PRFP);
    float*  xqf  = (float*)(smem + OFF_XQ);
    float*  wihs = (float*)(smem + OFF_WIH);
    float4* w04  = (float4*)(smem + OFF_W04);
    float*  wo   = (float*)(smem + OFF_WO);
    float2* b2   = (float2*)(smem + OFF_B2);

    const int tid       = threadIdx.x;
    const uint32_t rank = (uint32_t)(blockIdx.x & 1);
    const uint32_t peer = rank ^ 1u;
    const int cluster   = blockIdx.x >> 1;
    const int row0      = cluster * 4;

    const uint32_t smem_b = (uint32_t)__cvta_generic_to_shared(smem);
    const uint32_t mbar_b = smem_b + OFF_MBAR;
    uint32_t peer_b;
    asm("mapa.shared::cluster.u32 %0, %1, %2;" : "=r"(peer_b) : "r"(smem_b), "r"(peer));
    const uint32_t peer_mbar = peer_b + OFF_MBAR;

    // ---------- roles ----------
    const bool active = (tid < 328);
    const int u = (tid >= 164) ? 1 : 0;        // k sub-slot within each half
    const int g = active ? (tid - u * 164) : 0;
    const int prank = (int)(rank ^ 1u);

    // ---------- one-time init ----------
    ull wLA[RPW], wLB[RPW], wPA[RPW], wPB[RPW];
    if (active) {
        int gt  = g / JH;
        int jj0 = g - gt * JH;
        int RA  = gt * Hh + (int)rank * JH + jj0;        // gate i (gt0) / f (gt1)
        int RB  = (gt + 2) * Hh + (int)rank * JH + jj0;  // gate g / o
        const ull* wrA = (const ull*)(Whh + (size_t)RA * Hh);
        const ull* wrB = (const ull*)(Whh + (size_t)RB * Hh);
#pragma unroll
        for (int w = 0; w < 2; w++) {
            int half = w ? prank : (int)rank;
            int base = half * 41 + u * 21;
#pragma unroll
            for (int kk = 0; kk < 21; kk++) {
                bool real = (u * 21 + kk) < 41;
                ull vA = real ? wrA[base + kk] : 0ull;
                ull vB = real ? wrB[base + kk] : 0ull;
                if (kk < RPW) {
                    if (w == 0) { wLA[kk] = vA; wLB[kk] = vB; }
                    else        { wPA[kk] = vA; wPB[kk] = vB; }
                } else {
                    Wsm2[(w * SPW + kk - RPW) * 328 + tid] = make_ulonglong2(vA, vB);
                }
            }
        }
        if (u == 0) {
#pragma unroll
            for (int i = 1; i < 8; i++) {
                wihs[(0 * 7 + i - 1) * 164 + g] = Wih[RA * 8 + i];
                wihs[(1 * 7 + i - 1) * 164 + g] = Wih[RB * 8 + i];
            }
            b2[g] = make_float2(bih[RA] + bhh[RA], bih[RB] + bhh[RB]);
        }
    }
    if (tid < JH) {
        int base = (int)rank * JH + tid;
        w04[tid] = make_float4(Wih[(0 * Hh + base) * 8], Wih[(1 * Hh + base) * 8],
                               Wih[(2 * Hh + base) * 8], Wih[(3 * Hh + base) * 8]);
        wo[tid] = Wout[base];
    }
    for (int idx = tid; idx < (SZ_HQ / 4); idx += NTH)
        ((float*)(smem + OFF_HQ))[idx] = 0.f;
    for (int idx = tid; idx < (SZ_PW / 4); idx += NTH) pwf[idx] = 0.f;
    if (tid < 8) prfp[tid] = 0.f;
    if (tid < 32) {
        int i = tid >> 2, r = tid & 3;
        xqf[(0 * 8 + i) * 4 + r] = x[((size_t)((row0 + r) * Tt)) * 8 + i];
    }
    if (tid == 0) {
        asm volatile("mbarrier.init.shared.b64 [%0], 68;" :: "r"(mbar_b) : "memory");
        asm volatile("mbarrier.init.shared.b64 [%0], 68;" :: "r"(mbar_b + 8) : "memory");
    }
    const float bout_r = bout[0];
    float c_r = 0.f;
    const int jj = tid >> 2, rr = tid & 3;
    const int wid = tid >> 5, lane = tid & 31;
    int ph0 = 0, ph1 = 0;

    __syncthreads();
    asm volatile("barrier.cluster.arrive.aligned;" ::: "memory");
    asm volatile("barrier.cluster.wait.aligned;" ::: "memory");

    for (int t = 0; t < Tt; ++t) {
        const int cur = t & 1;
        const int nxt = cur ^ 1;

        // ---- crew: vectorized push of h[cur] local-half + pred sums to peer ----
        if (t) {
            if (tid < 64) {
                uint32_t off = (uint32_t)(OFF_HQ + cur * HBUF + (int)rank * 1312);
                st_remote_u64(peer_b + off + (uint32_t)(tid * 8),
                              ld_smem_u64(smem_b + off + (uint32_t)(tid * 8)));
                st_remote_u64(peer_b + off + (uint32_t)((tid + 64) * 8),
                              ld_smem_u64(smem_b + off + (uint32_t)((tid + 64) * 8)));
                if (tid < 36)
                    st_remote_u64(peer_b + off + (uint32_t)((tid + 128) * 8),
                                  ld_smem_u64(smem_b + off + (uint32_t)((tid + 128) * 8)));
                mbar_arrive_release(peer_mbar + (uint32_t)(cur * 8));
            } else if (tid < 68) {
                int r = tid - 64;
                float s = 0.f;
#pragma unroll
                for (int w = 0; w < 11; w++) s += pwf[nxt * 44 + w * 4 + r];
                st_remote_f32d(peer_b + (uint32_t)(OFF_PRFP + (nxt * 4 + r) * 4), s);
                mbar_arrive_release(peer_mbar + (uint32_t)(cur * 8));
            }
        }

        // ---- phase L: GEMV over LOCAL k sub-window (21 k-pairs) ----
        ull acc[8];   // [0..3]=row A r0..3, [4..7]=row B
        if (active) {
            if (u == 0) {
                float2 bb = b2[g];
                float a0 = bb.x, a1 = bb.x, a2 = bb.x, a3 = bb.x;
                float b0 = bb.y, b1 = bb.y, b2v = bb.y, b3 = bb.y;
                const float4* xv4 = (const float4*)(smem + OFF_XQ + cur * 128);
#pragma unroll
                for (int i = 1; i < 8; i++) {
                    float4 xv = xv4[i];
                    float wA = wihs[(0 * 7 + i - 1) * 164 + g];
                    float wB = wihs[(1 * 7 + i - 1) * 164 + g];
                    a0 += wA * xv.x; a1 += wA * xv.y; a2 += wA * xv.z; a3 += wA * xv.w;
                    b0 += wB * xv.x; b1 += wB * xv.y; b2v += wB * xv.z; b3 += wB * xv.w;
                }
                acc[0] = pack2_(a0, 0.f); acc[1] = pack2_(a1, 0.f);
                acc[2] = pack2_(a2, 0.f); acc[3] = pack2_(a3, 0.f);
                acc[4] = pack2_(b0, 0.f); acc[5] = pack2_(b1, 0.f);
                acc[6] = pack2_(b2v, 0.f); acc[7] = pack2_(b3, 0.f);
            } else {
#pragma unroll
                for (int q = 0; q < 8; q++) acc[q] = 0ull;
            }
            const char* hbL = smem + OFF_HQ + cur * HBUF + ((int)rank * 41 + u * 21) * 32;
#pragma unroll
            for (int kk = 0; kk < RPW; kk++) {
                ulonglong2 h01 = *(const ulonglong2*)(hbL + kk * 32);
                ulonglong2 h23 = *(const ulonglong2*)(hbL + kk * 32 + 16);
                fma2_(acc[0], wLA[kk], h01.x); fma2_(acc[4], wLB[kk], h01.x);
                fma2_(acc[1], wLA[kk], h01.y); fma2_(acc[5], wLB[kk], h01.y);
                fma2_(acc[2], wLA[kk], h23.x); fma2_(acc[6], wLB[kk], h23.x);
                fma2_(acc[3], wLA[kk], h23.y); fma2_(acc[7], wLB[kk], h23.y);
            }
#pragma unroll
            for (int kk = RPW; kk < 21; kk++) {
                ulonglong2 w2 = Wsm2[(0 * SPW + kk - RPW) * 328 + tid];
                ulonglong2 h01 = *(const ulonglong2*)(hbL + kk * 32);
                ulonglong2 h23 = *(const ulonglong2*)(hbL + kk * 32 + 16);
                fma2_(acc[0], w2.x, h01.x); fma2_(acc[4], w2.y, h01.x);
                fma2_(acc[1], w2.x, h01.y); fma2_(acc[5], w2.y, h01.y);
                fma2_(acc[2], w2.x, h23.x); fma2_(acc[6], w2.y, h23.x);
                fma2_(acc[3], w2.x, h23.y); fma2_(acc[7], w2.y, h23.y);
            }
        }

        // ---- wait for peer h-half + pred (pushed this step by peer crew) ----
        if (t && (active || (tid >= 352 && tid < 356))) {
            uint32_t p = cur ? (uint32_t)ph1 : (uint32_t)ph0;
            mbar_wait(mbar_b + (uint32_t)(cur * 8), p);
            if (cur) ph1 ^= 1; else ph0 ^= 1;
        }

        if (active) {
            // ---- phase P: GEMV over PEER k sub-window (21 k-pairs) ----
            const char* hbP = smem + OFF_HQ + cur * HBUF + (prank * 41 + u * 21) * 32;
#pragma unroll
            for (int kk = 0; kk < RPW; kk++) {
                ulonglong2 h01 = *(const ulonglong2*)(hbP + kk * 32);
                ulonglong2 h23 = *(const ulonglong2*)(hbP + kk * 32 + 16);
                fma2_(acc[0], wPA[kk], h01.x); fma2_(acc[4], wPB[kk], h01.x);
                fma2_(acc[1], wPA[kk], h01.y); fma2_(acc[5], wPB[kk], h01.y);
                fma2_(acc[2], wPA[kk], h23.x); fma2_(acc[6], wPB[kk], h23.x);
                fma2_(acc[3], wPA[kk], h23.y); fma2_(acc[7], wPB[kk], h23.y);
            }
#pragma unroll
            for (int kk = RPW; kk < 21; kk++) {
                ulonglong2 w2 = Wsm2[(1 * SPW + kk - RPW) * 328 + tid];
                ulonglong2 h01 = *(const ulonglong2*)(hbP + kk * 32);
                ulonglong2 h23 = *(const ulonglong2*)(hbP + kk * 32 + 16);
                fma2_(acc[0], w2.x, h01.x); fma2_(acc[4], w2.y, h01.x);
                fma2_(acc[1], w2.x, h01.y); fma2_(acc[5], w2.y, h01.y);
                fma2_(acc[2], w2.x, h23.x); fma2_(acc[6], w2.y, h23.x);
                fma2_(acc[3], w2.x, h23.y); fma2_(acc[7], w2.y, h23.y);
            }
            float lo, hi;
            float4 vA, vB;
            unpack2_(acc[0], lo, hi); vA.x = lo + hi;
            unpack2_(acc[1], lo, hi); vA.y = lo + hi;
            unpack2_(acc[2], lo, hi); vA.z = lo + hi;
            unpack2_(acc[3], lo, hi); vA.w = lo + hi;
            unpack2_(acc[4], lo, hi); vB.x = lo + hi;
            unpack2_(acc[5], lo, hi); vB.y = lo + hi;
            unpack2_(acc[6], lo, hi); vB.z = lo + hi;
            unpack2_(acc[7], lo, hi); vB.w = lo + hi;
            gb4[(u * 2 + 0) * 164 + g] = vA;
            gb4[(u * 2 + 1) * 164 + g] = vB;
        } else if (tid >= 352 && tid < 356) {
            // ---- pred finalize + anomaly fix + outputs ----
            int r = tid - 352, row = row0 + r;
            if (t > 0) {
                float sown = 0.f;
#pragma unroll
                for (int w = 0; w < 11; w++) sown += pwf[nxt * 44 + w * 4 + r];
                float pred = sown + prfp[nxt * 4 + r] + bout_r;
                float x0raw = xqf[(cur * 8 + 0) * 4 + r];
                float flag = 0.f, x0 = x0raw;
                if (fabsf(pred - x0raw) > 0.1f) { x0 = pred; flag = 1.f; }
                xqf[(cur * 8 + 0) * 4 + r] = x0;
                if (rank == 0) {
                    out[(size_t)row * Tt + (t - 1)] = pred;
                    out[(size_t)Bb * Tt + (size_t)row * Tt + t] = flag;
                }
            } else if (rank == 0) {
                out[(size_t)Bb * Tt + (size_t)row * Tt] = 0.f;
            }
        } else if (tid >= 360 && tid < 368 && (t + 1 < Tt)) {
            // ---- x prefetch (no wait needed) ----
            int i = tid - 360;
#pragma unroll
            for (int r = 0; r < 4; r++)
                xqf[(nxt * 8 + i) * 4 + r] =
                    x[((size_t)((row0 + r) * Tt + t + 1)) * 8 + i];
        }
        __syncthreads();   // gate partials + fixed x0 published

        // ---- activation, state update, LOCAL h store, pred partials ----
        if (active) {
            float x0 = xqf[(cur * 8 + 0) * 4 + rr];
            float4 wz = w04[jj];
            float gi = gbf[((0 * 2 + 0) * 164 + jj) * 4 + rr]
                     + gbf[((1 * 2 + 0) * 164 + jj) * 4 + rr] + wz.x * x0;
            float gF = gbf[((0 * 2 + 0) * 164 + jj + 82) * 4 + rr]
                     + gbf[((1 * 2 + 0) * 164 + jj + 82) * 4 + rr] + wz.y * x0;
            float gg = gbf[((0 * 2 + 1) * 164 + jj) * 4 + rr]
                     + gbf[((1 * 2 + 1) * 164 + jj) * 4 + rr] + wz.z * x0;
            float go = gbf[((0 * 2 + 1) * 164 + jj + 82) * 4 + rr]
                     + gbf[((1 * 2 + 1) * 164 + jj + 82) * 4 + rr] + wz.w * x0;
            float iv = sigmoidf_(gi);
            float fv = sigmoidf_(gF);
            float gv = tanhf(gg);
            float ov = sigmoidf_(go);
            c_r = fv * c_r + iv * gv;
            float hn = ov * tanhf(c_r);

            int kg = (int)rank * JH + jj;
            *(float*)(smem + OFF_HQ + nxt * HBUF
                      + (kg >> 1) * 32 + rr * 8 + (kg & 1) * 4) = hn;   // local only

            float p = hn * wo[jj];
            if (wid < 10) {
                p += __shfl_xor_sync(0xffffffffu, p, 16);
                p += __shfl_xor_sync(0xffffffffu, p, 8);
                p += __shfl_xor_sync(0xffffffffu, p, 4);
            } else {
                p += __shfl_xor_sync(0xffu, p, 4);
            }
            if (lane < 4) pwf[cur * 44 + wid * 4 + lane] = p;
        }
        __syncthreads();   // h[nxt] + pwf[cur] published locally
    }

    // ---- tail: push final pred sums (parity 1), write column Tt-1 ----
    if (tid < 64) {
        mbar_arrive_release(peer_mbar);
    } else if (tid < 68) {
        int r = tid - 64;
        float s = 0.f;
#pragma unroll
        for (int w = 0; w < 11; w++) s += pwf[1 * 44 + w * 4 + r];
        st_remote_f32d(peer_b + (uint32_t)(OFF_PRFP + (1 * 4 + r) * 4), s);
        mbar_arrive_release(peer_mbar);
    }
    if (tid >= 352 && tid < 356) {
        mbar_wait(mbar_b, (uint32_t)ph0);
        if (rank == 0) {
            int r = tid - 352;
            float sown = 0.f;
#pragma unroll
            for (int w = 0; w < 11; w++) sown += pwf[1 * 44 + w * 4 + r];
            float pred = sown + prfp[1 * 4 + r] + bout_r;
            out[(size_t)(row0 + r) * Tt + (Tt - 1)] = pred;
        }
    }
}

extern "C" void kernel_launch(void* const* d_in, const int* in_sizes, int n_in,
                              void* d_out, int out_size) {
    (void)in_sizes; (void)n_in; (void)out_size;
    cudaFuncSetAttribute(lstm_anom_kernel,
                         cudaFuncAttributeMaxDynamicSharedMemorySize, SMEM_TOTAL);
    lstm_anom_kernel<<<NCTA, NTH, SMEM_TOTAL>>>(
        (const float*)d_in[0],   // x
        (const float*)d_in[1],   // W_ih
        (const float*)d_in[2],   // W_hh
        (const float*)d_in[3],   // b_ih
        (const float*)d_in[4],   // b_hh
        (const float*)d_in[5],   // W_out
        (const float*)d_in[6],   // b_out
        (float*)d_out);
}